// round 1
// baseline (speedup 1.0000x reference)
#include <cuda_runtime.h>
#include <cuda_bf16.h>
#include <cstdint>

// Problem constants
#define NB   16      // batch
#define TT   8192    // time steps
#define NX   256     // modal state dim
#define NU   32      // input dim
#define NY   32      // output dim
#define LCH  128     // scan chunk length
#define NC   64      // number of chunks (TT / LCH)

// ---------------- device scratch (no runtime allocation allowed) -----------
__device__ float g_BzT[NU * NX];        // BzT[u][n] = (Q^T Bmat)[n][u]
__device__ float g_CzT[NX * NY];        // CzT[n][y] = (C Q)[y][n]
__device__ float g_z0 [NB * NX];        // modal initial state  x0 @ Q
__device__ float g_DT [NU * NY];        // DT[k][y] = D[y][k]
__device__ float g_lampow[LCH * NX];    // lampow[j][n] = lam[n]^(j+1)
__device__ float g_lamL[NX];            // lam[n]^LCH
__device__ float g_w  [(size_t)NB * TT * NX];   // local chunk scans (134 MB)
__device__ float g_zbprev[NB * NC * NX];        // boundary state feeding chunk c

// ---------------- K0: setup (modal transforms, tables) ----------------------
__global__ void k0_prep(const float* __restrict__ x0,
                        const float* __restrict__ Q,
                        const float* __restrict__ lam,
                        const float* __restrict__ Bmat,
                        const float* __restrict__ C,
                        const float* __restrict__ D)
{
    int n = threadIdx.x;          // 0..255
    int task = blockIdx.x;

    if (task < 32) {
        // BzT row u: Bz[n][u] = sum_i Q[i][n] * Bmat[i][u]
        int u = task;
        float s = 0.f;
        #pragma unroll 8
        for (int i = 0; i < NX; i++)
            s = fmaf(Q[i * NX + n], Bmat[i * NU + u], s);
        g_BzT[u * NX + n] = s;
    } else if (task < 64) {
        // CzT column y: Cz[y][n] = sum_i C[y][i] * Q[i][n]
        int y = task - 32;
        float s = 0.f;
        #pragma unroll 8
        for (int i = 0; i < NX; i++)
            s = fmaf(C[y * NX + i], Q[i * NX + n], s);
        g_CzT[n * NY + y] = s;
    } else if (task < 80) {
        // z0 row b: z0[b][n] = sum_i x0[b][i] * Q[i][n]
        int b = task - 64;
        float s = 0.f;
        #pragma unroll 8
        for (int i = 0; i < NX; i++)
            s = fmaf(x0[b * NX + i], Q[i * NX + n], s);
        g_z0[b * NX + n] = s;
    } else {
        // lam power table + D transpose
        float l = lam[n];
        float p = l;
        for (int j = 0; j < LCH; j++) {
            g_lampow[j * NX + n] = p;       // lam^(j+1)
            if (j == LCH - 1) g_lamL[n] = p;
            p *= l;
        }
        for (int e = threadIdx.x; e < NY * NU; e += blockDim.x) {
            int y = e / NU, k = e % NU;
            g_DT[k * NY + y] = D[y * NU + k];
        }
    }
}

// ---------------- K1: per-chunk local scan (v computed on the fly) ----------
__global__ void __launch_bounds__(256) k1_scan(const float* __restrict__ u,
                                               const float* __restrict__ lam)
{
    int c = blockIdx.x;           // chunk
    int b = blockIdx.y;           // batch
    int n = threadIdx.x;          // modal index 0..255

    __shared__ float4 us4[LCH * (NU / 4)];   // u chunk, 16 KB

    // cooperative load of u[b, c*L .. c*L+L, :]
    const float4* ug = (const float4*)(u + ((size_t)b * TT + (size_t)c * LCH) * NU);
    for (int i = threadIdx.x; i < LCH * (NU / 4); i += 256)
        us4[i] = ug[i];

    // Bz row for this modal index (coalesced reads of BzT)
    float bz[NU];
    #pragma unroll
    for (int k = 0; k < NU; k++) bz[k] = g_BzT[k * NX + n];

    float ln  = lam[n];
    float z0c = (c == 0) ? ln * g_z0[b * NX + n] : 0.f;
    float w   = 0.f;

    __syncthreads();

    float* wp = g_w + ((size_t)b * TT + (size_t)c * LCH) * NX + n;

    #pragma unroll 4
    for (int j = 0; j < LCH; j++) {
        float v = (j == 0) ? z0c : 0.f;
        #pragma unroll
        for (int kk = 0; kk < NU / 4; kk++) {
            float4 q = us4[j * (NU / 4) + kk];   // broadcast, conflict-free
            v = fmaf(q.x, bz[4 * kk + 0], v);
            v = fmaf(q.y, bz[4 * kk + 1], v);
            v = fmaf(q.z, bz[4 * kk + 2], v);
            v = fmaf(q.w, bz[4 * kk + 3], v);
        }
        w = fmaf(ln, w, v);
        wp[(size_t)j * NX] = w;                  // coalesced over n
    }
}

// ---------------- K2: chain chunk boundaries --------------------------------
__global__ void k2_boundary()
{
    int b = blockIdx.x;
    int n = threadIdx.x;
    float zb = 0.f;
    float lL = g_lamL[n];
    const float* wp = g_w + ((size_t)b * TT + (LCH - 1)) * NX + n;
    float* zp = g_zbprev + ((size_t)b * NC) * NX + n;
    for (int c = 0; c < NC; c++) {
        zp[(size_t)c * NX] = zb;                          // state entering chunk c
        float S = wp[(size_t)c * LCH * NX];               // local chunk-end value
        zb = fmaf(lL, zb, S);
    }
}

// ---------------- K3: correction + output GEMM ------------------------------
__global__ void __launch_bounds__(256) k3_out(const float* __restrict__ u,
                                              float* __restrict__ y)
{
    int c  = blockIdx.x;
    int b  = blockIdx.y;
    int tx = threadIdx.x & 31;    // output channel y
    int ty = threadIdx.x >> 5;    // j-group 0..7 (16 t-rows each)

    __shared__ float zs [32 * 132];   // z tile, [n_local][j], padded
    __shared__ float czs[32 * 32];    // CzT tile [n_local][y]
    __shared__ float dts[NU * NY];    // DT
    __shared__ float us [LCH * NU];   // u rows for this output tile

    float acc[16];
    #pragma unroll
    for (int i = 0; i < 16; i++) acc[i] = 0.f;

    const float* zbp  = g_zbprev + ((size_t)b * NC + c) * NX;
    const size_t wbase = ((size_t)b * TT + (size_t)c * LCH) * NX;

    for (int nt = 0; nt < NX / 32; nt++) {
        int n0 = nt * 32;
        __syncthreads();
        // CzT tile (contiguous 1024 floats)
        for (int e = threadIdx.x; e < 1024; e += 256)
            czs[e] = g_CzT[n0 * NY + e];
        // corrected z tile, transposed into [n][j]
        #pragma unroll
        for (int i = 0; i < 16; i++) {
            int e  = threadIdx.x + i * 256;
            int j  = e >> 5;
            int nn = e & 31;
            float wv = g_w[wbase + (size_t)j * NX + n0 + nn];   // coalesced over nn
            float pw = g_lampow[j * NX + n0 + nn];
            zs[nn * 132 + j] = fmaf(pw, zbp[n0 + nn], wv);
        }
        __syncthreads();
        #pragma unroll 4
        for (int nn = 0; nn < 32; nn++) {
            float czv = czs[nn * 32 + tx];                       // conflict-free
            const float4* zrow = (const float4*)&zs[nn * 132 + ty * 16]; // broadcast
            #pragma unroll
            for (int q4 = 0; q4 < 4; q4++) {
                float4 z4 = zrow[q4];
                acc[q4 * 4 + 0] = fmaf(z4.x, czv, acc[q4 * 4 + 0]);
                acc[q4 * 4 + 1] = fmaf(z4.y, czv, acc[q4 * 4 + 1]);
                acc[q4 * 4 + 2] = fmaf(z4.z, czv, acc[q4 * 4 + 2]);
                acc[q4 * 4 + 3] = fmaf(z4.w, czv, acc[q4 * 4 + 3]);
            }
        }
    }

    // feedthrough term  y += u @ D^T   (outputs at t = c*L + j + 1)
    __syncthreads();
    for (int e = threadIdx.x; e < NU * NY; e += 256) dts[e] = g_DT[e];
    {
        const float* ug = u + ((size_t)b * TT + (size_t)c * LCH + 1) * NU;
        int limit = (c == NC - 1) ? (LCH - 1) * NU : LCH * NU;   // t=T row is OOB
        for (int e = threadIdx.x; e < LCH * NU; e += 256)
            us[e] = (e < limit) ? ug[e] : 0.f;
    }
    __syncthreads();
    #pragma unroll 4
    for (int k = 0; k < NU; k++) {
        float dv = dts[k * NY + tx];
        #pragma unroll
        for (int jj = 0; jj < 16; jj++)
            acc[jj] = fmaf(us[(ty * 16 + jj) * NU + k], dv, acc[jj]);
    }

    // store y[b, t=c*L+j+1, tx]
    float* yp = y + ((size_t)b * TT + (size_t)c * LCH + 1) * NY + tx;
    #pragma unroll
    for (int jj = 0; jj < 16; jj++) {
        int j = ty * 16 + jj;
        if (c * LCH + j + 1 < TT) yp[(size_t)j * NY] = acc[jj];
    }

    // t = 0 output uses z0 directly
    if (c == 0 && threadIdx.x < NY) {
        int yy = threadIdx.x;
        float s = 0.f;
        #pragma unroll 8
        for (int i = 0; i < NX; i++)
            s = fmaf(g_CzT[i * NY + yy], g_z0[b * NX + i], s);
        #pragma unroll
        for (int k = 0; k < NU; k++)
            s = fmaf(g_DT[k * NY + yy], u[((size_t)b * TT) * NU + k], s);
        y[((size_t)b * TT) * NY + yy] = s;
    }
}

// ---------------- launch -----------------------------------------------------
extern "C" void kernel_launch(void* const* d_in, const int* in_sizes, int n_in,
                              void* d_out, int out_size)
{
    const float* x0   = (const float*)d_in[0];   // (16, 256)
    const float* u    = (const float*)d_in[1];   // (16, 8192, 32)
    const float* Q    = (const float*)d_in[2];   // (256, 256)
    const float* lam  = (const float*)d_in[3];   // (256,)
    const float* Bmat = (const float*)d_in[4];   // (256, 32)
    const float* C    = (const float*)d_in[5];   // (32, 256)
    const float* D    = (const float*)d_in[6];   // (32, 32)
    float* y = (float*)d_out;                    // (16, 8192, 32)

    k0_prep<<<81, 256>>>(x0, Q, lam, Bmat, C, D);
    k1_scan<<<dim3(NC, NB), 256>>>(u, lam);
    k2_boundary<<<NB, 256>>>();
    k3_out<<<dim3(NC, NB), 256>>>(u, y);
}

// round 2
// speedup vs baseline: 1.1627x; 1.1627x over previous
#include <cuda_runtime.h>
#include <cuda_bf16.h>
#include <cstdint>

// Problem constants
#define NB   16      // batch
#define TT   8192    // time steps
#define NX   256     // modal state dim
#define NU   32      // input dim
#define NY   32      // output dim
#define LCH  128     // scan chunk length
#define NC   64      // number of chunks (TT / LCH)

// ---------------- f32x2 packed helpers (sm_103a FFMA2 path) -----------------
__device__ __forceinline__ unsigned long long fma2(unsigned long long a,
                                                   unsigned long long b,
                                                   unsigned long long c) {
    unsigned long long d;
    asm("fma.rn.f32x2 %0, %1, %2, %3;" : "=l"(d) : "l"(a), "l"(b), "l"(c));
    return d;
}
__device__ __forceinline__ unsigned long long pack2(float a, float b) {
    unsigned long long r;
    asm("mov.b64 %0, {%1, %2};" : "=l"(r) : "f"(a), "f"(b));
    return r;
}
__device__ __forceinline__ void unpack2(unsigned long long v, float& a, float& b) {
    asm("mov.b64 {%0, %1}, %2;" : "=f"(a), "=f"(b) : "l"(v));
}

// ---------------- device scratch (no runtime allocation allowed) -----------
__device__ float g_BzT[NU * NX];        // BzT[u][n] = (Q^T Bmat)[n][u]
__device__ float g_CzT[NX * NY];        // CzT[n][y] = (C Q)[y][n]
__device__ float g_z0 [NB * NX];        // modal initial state  x0 @ Q
__device__ float g_DT [NU * NY];        // DT[k][y] = D[y][k]
__device__ float g_lampow[LCH * NX];    // lampow[j][n] = lam[n]^(j+1)
__device__ float g_lamL[NX];            // lam[n]^LCH
__device__ float g_w  [(size_t)NB * TT * NX];   // local chunk scans (134 MB)
__device__ float g_zbprev[NB * NC * NX];        // boundary state feeding chunk c

// ---------------- K0: setup (modal transforms, tables) ----------------------
__global__ void k0_prep(const float* __restrict__ x0,
                        const float* __restrict__ Q,
                        const float* __restrict__ lam,
                        const float* __restrict__ Bmat,
                        const float* __restrict__ C,
                        const float* __restrict__ D)
{
    int n = threadIdx.x;          // 0..255
    int task = blockIdx.x;

    if (task < 32) {
        int u = task;
        float s = 0.f;
        #pragma unroll 8
        for (int i = 0; i < NX; i++)
            s = fmaf(Q[i * NX + n], Bmat[i * NU + u], s);
        g_BzT[u * NX + n] = s;
    } else if (task < 64) {
        int y = task - 32;
        float s = 0.f;
        #pragma unroll 8
        for (int i = 0; i < NX; i++)
            s = fmaf(C[y * NX + i], Q[i * NX + n], s);
        g_CzT[n * NY + y] = s;
    } else if (task < 80) {
        int b = task - 64;
        float s = 0.f;
        #pragma unroll 8
        for (int i = 0; i < NX; i++)
            s = fmaf(x0[b * NX + i], Q[i * NX + n], s);
        g_z0[b * NX + n] = s;
    } else {
        float l = lam[n];
        float p = l;
        for (int j = 0; j < LCH; j++) {
            g_lampow[j * NX + n] = p;       // lam^(j+1)
            if (j == LCH - 1) g_lamL[n] = p;
            p *= l;
        }
        for (int e = threadIdx.x; e < NY * NU; e += blockDim.x) {
            int y = e / NU, k = e % NU;
            g_DT[k * NY + y] = D[y * NU + k];
        }
    }
}

// ---------------- K1: per-chunk local scan (pair-dot FFMA2) -----------------
__global__ void __launch_bounds__(256) k1_scan(const float* __restrict__ u,
                                               const float* __restrict__ lam)
{
    int c = blockIdx.x;           // chunk
    int b = blockIdx.y;           // batch
    int n = threadIdx.x;          // modal index 0..255

    __shared__ float4 us4[LCH * (NU / 4)];   // u chunk, 16 KB

    const float4* ug = (const float4*)(u + ((size_t)b * TT + (size_t)c * LCH) * NU);
    for (int i = threadIdx.x; i < LCH * (NU / 4); i += 256)
        us4[i] = ug[i];

    // Bz row packed as 16 (k, k+1) pairs
    unsigned long long bz2[NU / 2];
    #pragma unroll
    for (int k = 0; k < NU / 2; k++)
        bz2[k] = pack2(g_BzT[(2 * k) * NX + n], g_BzT[(2 * k + 1) * NX + n]);

    float ln  = lam[n];
    float z0c = (c == 0) ? ln * g_z0[b * NX + n] : 0.f;
    float w   = 0.f;

    __syncthreads();

    float* wp = g_w + ((size_t)b * TT + (size_t)c * LCH) * NX + n;
    const ulonglong2* usll = (const ulonglong2*)us4;

    #pragma unroll 4
    for (int j = 0; j < LCH; j++) {
        unsigned long long aA = 0ull, aB = 0ull;      // two packed accumulators
        #pragma unroll
        for (int kk = 0; kk < NU / 4; kk++) {
            ulonglong2 q = usll[j * (NU / 4) + kk];   // broadcast, conflict-free
            aA = fma2(q.x, bz2[2 * kk + 0], aA);
            aB = fma2(q.y, bz2[2 * kk + 1], aB);
        }
        float a0, a1, b0, b1;
        unpack2(aA, a0, a1);
        unpack2(aB, b0, b1);
        float v = (a0 + a1) + (b0 + b1);
        if (j == 0) v += z0c;
        w = fmaf(ln, w, v);
        wp[(size_t)j * NX] = w;                       // coalesced over n
    }
}

// ---------------- K2: chain chunk boundaries (MLP-prefetched) ---------------
__global__ void k2_boundary()
{
    int b = blockIdx.x;
    int n = threadIdx.x;
    float lL = g_lamL[n];
    const float* wp = g_w + ((size_t)b * TT + (LCH - 1)) * NX + n;
    float S[NC];
    #pragma unroll
    for (int c = 0; c < NC; c++)
        S[c] = wp[(size_t)c * LCH * NX];              // 64 independent LDGs
    float* zp = g_zbprev + ((size_t)b * NC) * NX + n;
    float zb = 0.f;
    #pragma unroll
    for (int c = 0; c < NC; c++) {
        zp[(size_t)c * NX] = zb;                      // state entering chunk c
        zb = fmaf(lL, zb, S[c]);
    }
}

// ---------------- K3: correction + fused output GEMM (FFMA2) ----------------
// Thread tile: 4t x 4y. Feedthrough u@D^T is folded in as a 9th "modal" tile.
__global__ void __launch_bounds__(256) k3_out(const float* __restrict__ u,
                                              float* __restrict__ y)
{
    int c  = blockIdx.x;
    int b  = blockIdx.y;
    int tx = threadIdx.x & 7;     // y-group (4 outputs)
    int tt = threadIdx.x >> 3;    // t-group (4 time rows), 0..31

    __shared__ float zs [32 * 132];   // z tile [n_local][j], padded  (16.9 KB)
    __shared__ float czd[32 * 64];    // dup-pair Cz tile [n_local][y dup] (8 KB)

    unsigned long long acc2[2][4];    // [t-pair][yy], packed along t
    #pragma unroll
    for (int p = 0; p < 2; p++)
        #pragma unroll
        for (int q = 0; q < 4; q++) acc2[p][q] = 0ull;

    const float* zbp  = g_zbprev + ((size_t)b * NC + c) * NX;
    const size_t wbase = ((size_t)b * TT + (size_t)c * LCH) * NX;
    const float* ub = u + ((size_t)b * TT + (size_t)c * LCH + 1) * NU;
    const int ulimit = (c == NC - 1) ? (LCH - 1) * NU : LCH * NU;

    for (int nt = 0; nt < 9; nt++) {
        __syncthreads();
        if (nt < 8) {
            int n0 = nt * 32;
            // Cz tile, duplicated pairs: czd[nn][2y] = czd[nn][2y+1] = Cz
            for (int e = threadIdx.x; e < 1024; e += 256) {
                float v = g_CzT[n0 * NY + e];
                int nn = e >> 5, yy = e & 31;
                czd[nn * 64 + 2 * yy]     = v;
                czd[nn * 64 + 2 * yy + 1] = v;
            }
            // corrected z tile, transposed into [n][j]
            #pragma unroll
            for (int i = 0; i < 16; i++) {
                int e  = threadIdx.x + i * 256;
                int j  = e >> 5;
                int nn = e & 31;
                float wv = g_w[wbase + (size_t)j * NX + n0 + nn]; // coalesced
                float pw = g_lampow[j * NX + n0 + nn];
                zs[nn * 132 + j] = fmaf(pw, zbp[n0 + nn], wv);
            }
        } else {
            // feedthrough tile: zs <- u rows (t = c*L + j + 1), czd <- D^T dup
            for (int e = threadIdx.x; e < 1024; e += 256) {
                float v = g_DT[e];                    // [k][y]
                int nn = e >> 5, yy = e & 31;
                czd[nn * 64 + 2 * yy]     = v;
                czd[nn * 64 + 2 * yy + 1] = v;
            }
            #pragma unroll
            for (int i = 0; i < 16; i++) {
                int e  = threadIdx.x + i * 256;
                int j  = e >> 5;
                int kk = e & 31;
                float v = (e < ulimit) ? ub[e] : 0.f; // coalesced over kk
                zs[kk * 132 + j] = v;
            }
        }
        __syncthreads();

        const float* zrowbase = &zs[tt * 4];
        const float* crowbase = &czd[tx * 8];
        #pragma unroll 4
        for (int nn = 0; nn < 32; nn++) {
            ulonglong2 z2  = *(const ulonglong2*)(zrowbase + nn * 132); // (t0,t1),(t2,t3)
            ulonglong2 c01 = *(const ulonglong2*)(crowbase + nn * 64);      // y0,y1 dup
            ulonglong2 c23 = *(const ulonglong2*)(crowbase + nn * 64 + 4);  // y2,y3 dup
            acc2[0][0] = fma2(z2.x, c01.x, acc2[0][0]);
            acc2[1][0] = fma2(z2.y, c01.x, acc2[1][0]);
            acc2[0][1] = fma2(z2.x, c01.y, acc2[0][1]);
            acc2[1][1] = fma2(z2.y, c01.y, acc2[1][1]);
            acc2[0][2] = fma2(z2.x, c23.x, acc2[0][2]);
            acc2[1][2] = fma2(z2.y, c23.x, acc2[1][2]);
            acc2[0][3] = fma2(z2.x, c23.y, acc2[0][3]);
            acc2[1][3] = fma2(z2.y, c23.y, acc2[1][3]);
        }
    }

    // unpack and store: outputs at t = c*L + tt*4 + ti + 1, cols tx*4..tx*4+3
    float out[4][4];
    #pragma unroll
    for (int p = 0; p < 2; p++)
        #pragma unroll
        for (int q = 0; q < 4; q++)
            unpack2(acc2[p][q], out[2 * p][q], out[2 * p + 1][q]);

    #pragma unroll
    for (int ti = 0; ti < 4; ti++) {
        int t = c * LCH + tt * 4 + ti + 1;
        if (t < TT) {
            float4 v = make_float4(out[ti][0], out[ti][1], out[ti][2], out[ti][3]);
            *(float4*)&y[((size_t)b * TT + t) * NY + tx * 4] = v;
        }
    }

    // t = 0 output uses z0 directly
    if (c == 0 && threadIdx.x < NY) {
        int yy = threadIdx.x;
        float s = 0.f;
        #pragma unroll 8
        for (int i = 0; i < NX; i++)
            s = fmaf(g_CzT[i * NY + yy], g_z0[b * NX + i], s);
        #pragma unroll
        for (int k = 0; k < NU; k++)
            s = fmaf(g_DT[k * NY + yy], u[((size_t)b * TT) * NU + k], s);
        y[((size_t)b * TT) * NY + yy] = s;
    }
}

// ---------------- launch -----------------------------------------------------
extern "C" void kernel_launch(void* const* d_in, const int* in_sizes, int n_in,
                              void* d_out, int out_size)
{
    const float* x0   = (const float*)d_in[0];   // (16, 256)
    const float* u    = (const float*)d_in[1];   // (16, 8192, 32)
    const float* Q    = (const float*)d_in[2];   // (256, 256)
    const float* lam  = (const float*)d_in[3];   // (256,)
    const float* Bmat = (const float*)d_in[4];   // (256, 32)
    const float* C    = (const float*)d_in[5];   // (32, 256)
    const float* D    = (const float*)d_in[6];   // (32, 32)
    float* y = (float*)d_out;                    // (16, 8192, 32)

    k0_prep<<<81, 256>>>(x0, Q, lam, Bmat, C, D);
    k1_scan<<<dim3(NC, NB), 256>>>(u, lam);
    k2_boundary<<<NB, 256>>>();
    k3_out<<<dim3(NC, NB), 256>>>(u, y);
}

// round 4
// speedup vs baseline: 1.5717x; 1.3517x over previous
#include <cuda_runtime.h>
#include <cuda_bf16.h>
#include <cstdint>

// Problem constants
#define NB   16      // batch
#define TT   8192    // time steps
#define NX   256     // modal state dim
#define NU   32      // input dim
#define NY   32      // output dim
#define LCH  128     // scan chunk length
#define NC   64      // number of chunks (TT / LCH)
#define K3T  256     // t-rows per k3 block (2 chunks)

// ---------------- f32x2 packed helpers (sm_103a FFMA2 path) -----------------
__device__ __forceinline__ unsigned long long fma2(unsigned long long a,
                                                   unsigned long long b,
                                                   unsigned long long c) {
    unsigned long long d;
    asm("fma.rn.f32x2 %0, %1, %2, %3;" : "=l"(d) : "l"(a), "l"(b), "l"(c));
    return d;
}
__device__ __forceinline__ unsigned long long pack2(float a, float b) {
    unsigned long long r;
    asm("mov.b64 %0, {%1, %2};" : "=l"(r) : "f"(a), "f"(b));
    return r;
}
__device__ __forceinline__ void unpack2(unsigned long long v, float& a, float& b) {
    asm("mov.b64 {%0, %1}, %2;" : "=f"(a), "=f"(b) : "l"(v));
}

// ---------------- device scratch (no runtime allocation allowed) -----------
__device__ float g_BzT[NU * NX];        // BzT[u][n] = (Q^T Bmat)[n][u]
__device__ float g_CzT[NX * NY];        // CzT[n][y] = (C Q)[y][n]
__device__ float g_z0 [NB * NX];        // modal initial state  x0 @ Q
__device__ float g_DT [NU * NY];        // DT[k][y] = D[y][k]
__device__ float g_lampow[LCH * NX];    // lampow[j][n] = lam[n]^(j+1)
__device__ float g_lamL[NX];            // lam[n]^LCH
__device__ float g_w  [(size_t)NB * TT * NX];   // local chunk scans (134 MB)
__device__ float g_zbprev[NB * NC * NX];        // boundary state feeding chunk c

// ---------------- K0: setup (modal transforms, tables) ----------------------
__global__ void k0_prep(const float* __restrict__ x0,
                        const float* __restrict__ Q,
                        const float* __restrict__ lam,
                        const float* __restrict__ Bmat,
                        const float* __restrict__ C,
                        const float* __restrict__ D)
{
    int n = threadIdx.x;          // 0..255
    int task = blockIdx.x;

    if (task < 32) {
        int u = task;
        float s = 0.f;
        #pragma unroll 8
        for (int i = 0; i < NX; i++)
            s = fmaf(Q[i * NX + n], Bmat[i * NU + u], s);
        g_BzT[u * NX + n] = s;
    } else if (task < 64) {
        int y = task - 32;
        float s = 0.f;
        #pragma unroll 8
        for (int i = 0; i < NX; i++)
            s = fmaf(C[y * NX + i], Q[i * NX + n], s);
        g_CzT[n * NY + y] = s;
    } else if (task < 80) {
        int b = task - 64;
        float s = 0.f;
        #pragma unroll 8
        for (int i = 0; i < NX; i++)
            s = fmaf(x0[b * NX + i], Q[i * NX + n], s);
        g_z0[b * NX + n] = s;
    } else {
        float l = lam[n];
        float p = l;
        for (int j = 0; j < LCH; j++) {
            g_lampow[j * NX + n] = p;       // lam^(j+1)
            if (j == LCH - 1) g_lamL[n] = p;
            p *= l;
        }
        for (int e = threadIdx.x; e < NY * NU; e += blockDim.x) {
            int y = e / NU, k = e % NU;
            g_DT[k * NY + y] = D[y * NU + k];
        }
    }
}

// ---------------- K1: per-chunk local scan, 4 modal lanes per thread --------
__global__ void __launch_bounds__(64) k1_scan(const float* __restrict__ u,
                                              const float* __restrict__ lam)
{
    int c = blockIdx.x;           // chunk
    int b = blockIdx.y;           // batch
    int tid = threadIdx.x;        // 0..63; owns n = tid + 64*m, m=0..3

    __shared__ float4 us4[LCH * (NU / 4)];   // u chunk, 16 KB

    const float4* ug = (const float4*)(u + ((size_t)b * TT + (size_t)c * LCH) * NU);
    #pragma unroll
    for (int i = 0; i < 16; i++)
        us4[tid + i * 64] = ug[tid + i * 64];

    unsigned long long bz2[4][NU / 2];
    float ln[4], z0c[4], w[4];
    #pragma unroll
    for (int m = 0; m < 4; m++) {
        int n = tid + 64 * m;
        #pragma unroll
        for (int k = 0; k < NU / 2; k++)
            bz2[m][k] = pack2(g_BzT[(2 * k) * NX + n], g_BzT[(2 * k + 1) * NX + n]);
        ln[m]  = lam[n];
        z0c[m] = (c == 0) ? ln[m] * g_z0[b * NX + n] : 0.f;
        w[m]   = 0.f;
    }

    __syncthreads();

    float* wp = g_w + ((size_t)b * TT + (size_t)c * LCH) * NX + tid;
    const ulonglong2* usll = (const ulonglong2*)us4;

    #pragma unroll 2
    for (int j = 0; j < LCH; j++) {
        unsigned long long aA[4] = {0ull, 0ull, 0ull, 0ull};
        unsigned long long aB[4] = {0ull, 0ull, 0ull, 0ull};
        #pragma unroll
        for (int kk = 0; kk < NU / 4; kk++) {
            ulonglong2 q = usll[j * (NU / 4) + kk];   // broadcast
            #pragma unroll
            for (int m = 0; m < 4; m++) {
                aA[m] = fma2(q.x, bz2[m][2 * kk + 0], aA[m]);
                aB[m] = fma2(q.y, bz2[m][2 * kk + 1], aB[m]);
            }
        }
        #pragma unroll
        for (int m = 0; m < 4; m++) {
            float a0, a1, b0, b1;
            unpack2(aA[m], a0, a1);
            unpack2(aB[m], b0, b1);
            float v = (a0 + a1) + (b0 + b1);
            if (j == 0) v += z0c[m];
            w[m] = fmaf(ln[m], w[m], v);
            wp[(size_t)j * NX + 64 * m] = w[m];       // coalesced over tid
        }
    }
}

// ---------------- K2: chain chunk boundaries (MLP-prefetched) ---------------
__global__ void k2_boundary()
{
    int b = blockIdx.x;
    int n = threadIdx.x;
    float lL = g_lamL[n];
    const float* wp = g_w + ((size_t)b * TT + (LCH - 1)) * NX + n;
    float S[NC];
    #pragma unroll
    for (int c = 0; c < NC; c++)
        S[c] = wp[(size_t)c * LCH * NX];              // 64 independent LDGs
    float* zp = g_zbprev + ((size_t)b * NC) * NX + n;
    float zb = 0.f;
    #pragma unroll
    for (int c = 0; c < NC; c++) {
        zp[(size_t)c * NX] = zb;                      // state entering chunk c
        zb = fmaf(lL, zb, S[c]);
    }
}

// ---------------- K3: correction + fused output GEMM ------------------------
// Block: 128 threads, tile 256t x 32y, K = 256 modal + 32 feedthrough.
// Thread tile 8t x 8y (t-packed FFMA2).  lane = t-group, warp = y-group.
// z tile is XOR-swizzled: word(nn,t) = nn*256 + (((t>>2) ^ nn) << 2) + (t&3)
//  -> staging STS.128 and compute LDS.128 are both conflict-free and dense.
__global__ void __launch_bounds__(128) k3_out(const float* __restrict__ u,
                                              float* __restrict__ y)
{
    int bt  = blockIdx.x;          // 0..31, covers chunks 2bt, 2bt+1
    int b   = blockIdx.y;
    int t0  = bt * K3T;
    int lane = threadIdx.x & 31;   // t-group: t = 4*lane(+128)
    int wy   = threadIdx.x >> 5;   // y-group: y = 8*wy .. 8*wy+7

    __shared__ float zs [32 * 256];   // swizzled [nn][t] tile (32 KB)
    __shared__ float czs[32 * 32];    // cz tile [nn][y] (4 KB)

    unsigned long long acc[4][8];     // [t-pair][y], packed along t
    #pragma unroll
    for (int p = 0; p < 4; p++)
        #pragma unroll
        for (int q = 0; q < 8; q++) acc[p][q] = 0ull;

    const float* zb0 = g_zbprev + ((size_t)b * NC + 2 * bt) * NX;
    const float* zb1 = zb0 + NX;
    const size_t wbase = ((size_t)b * TT + t0) * NX;
    const float* ub = u + ((size_t)b * TT + t0 + 1) * NU;
    const int ulim = (bt == NC / 2 - 1) ? (K3T - 1) * NU : K3T * NU;

    int snn = threadIdx.x & 31;    // staging: row (modal or k index)
    int stg = threadIdx.x >> 5;    // staging: chunk group (16 chunks each)

    for (int nt = 0; nt < 9; nt++) {
        __syncthreads();
        if (nt < 8) {
            int n0 = nt * 32;
            for (int e = threadIdx.x; e < 1024; e += 128)
                czs[e] = g_CzT[n0 * NY + e];
            float zbv0 = zb0[n0 + snn];
            float zbv1 = zb1[n0 + snn];
            #pragma unroll 4
            for (int cc = 0; cc < 16; cc++) {
                int ch = stg * 16 + cc;              // chunk 0..63 (t = 4*ch)
                int tb = ch * 4;
                float zbv = (ch < 32) ? zbv0 : zbv1;
                const float* wrow = &g_w[wbase + (size_t)tb * NX + n0 + snn];
                const float* lrow = &g_lampow[(tb & (LCH - 1)) * NX + n0 + snn];
                float4 v;
                v.x = fmaf(lrow[0 * NX], zbv, wrow[0 * (size_t)NX]);
                v.y = fmaf(lrow[1 * NX], zbv, wrow[1 * (size_t)NX]);
                v.z = fmaf(lrow[2 * NX], zbv, wrow[2 * (size_t)NX]);
                v.w = fmaf(lrow[3 * NX], zbv, wrow[3 * (size_t)NX]);
                *(float4*)&zs[snn * 256 + ((ch ^ snn) << 2)] = v;
            }
        } else {
            for (int e = threadIdx.x; e < 1024; e += 128)
                czs[e] = g_DT[e];
            #pragma unroll 4
            for (int cc = 0; cc < 16; cc++) {
                int ch = stg * 16 + cc;
                int e0 = ch * 4 * NU + snn;          // u element (t*NU + k)
                float4 v;
                v.x = (e0 + 0 * NU < ulim) ? ub[e0 + 0 * NU] : 0.f;
                v.y = (e0 + 1 * NU < ulim) ? ub[e0 + 1 * NU] : 0.f;
                v.z = (e0 + 2 * NU < ulim) ? ub[e0 + 2 * NU] : 0.f;
                v.w = (e0 + 3 * NU < ulim) ? ub[e0 + 3 * NU] : 0.f;
                *(float4*)&zs[snn * 256 + ((ch ^ snn) << 2)] = v;
            }
        }
        __syncthreads();

        #pragma unroll 4
        for (int nn = 0; nn < 32; nn++) {
            // z: 8 t values as 2 dense LDS.128 (chunks lane and lane+32)
            ulonglong2 za = *(const ulonglong2*)&zs[nn * 256 + ((lane ^ nn) << 2)];
            ulonglong2 zb = *(const ulonglong2*)&zs[nn * 256 + (((lane + 32) ^ nn) << 2)];
            // cz: 8 y values, broadcast loads + in-register dup
            float4 c1 = *(const float4*)&czs[nn * 32 + wy * 8];
            float4 c2 = *(const float4*)&czs[nn * 32 + wy * 8 + 4];
            unsigned long long cd[8];
            cd[0] = pack2(c1.x, c1.x); cd[1] = pack2(c1.y, c1.y);
            cd[2] = pack2(c1.z, c1.z); cd[3] = pack2(c1.w, c1.w);
            cd[4] = pack2(c2.x, c2.x); cd[5] = pack2(c2.y, c2.y);
            cd[6] = pack2(c2.z, c2.z); cd[7] = pack2(c2.w, c2.w);
            #pragma unroll
            for (int q = 0; q < 8; q++) {
                acc[0][q] = fma2(za.x, cd[q], acc[0][q]);
                acc[1][q] = fma2(za.y, cd[q], acc[1][q]);
                acc[2][q] = fma2(zb.x, cd[q], acc[2][q]);
                acc[3][q] = fma2(zb.y, cd[q], acc[3][q]);
            }
        }
    }

    // store: pair p covers source t = tp, tp+1 -> outputs at t0+tsrc+1
    #pragma unroll
    for (int p = 0; p < 4; p++) {
        int tp = (p < 2) ? (4 * lane + 2 * p) : (LCH + 4 * lane + 2 * (p - 2));
        float lo[8], hi[8];
        #pragma unroll
        for (int q = 0; q < 8; q++) unpack2(acc[p][q], lo[q], hi[q]);
        int ta = t0 + tp + 1;
        if (ta < TT) {
            float4 o0 = make_float4(lo[0], lo[1], lo[2], lo[3]);
            float4 o1 = make_float4(lo[4], lo[5], lo[6], lo[7]);
            *(float4*)&y[((size_t)b * TT + ta) * NY + wy * 8]     = o0;
            *(float4*)&y[((size_t)b * TT + ta) * NY + wy * 8 + 4] = o1;
        }
        int tb2 = t0 + tp + 2;
        if (tb2 < TT) {
            float4 o0 = make_float4(hi[0], hi[1], hi[2], hi[3]);
            float4 o1 = make_float4(hi[4], hi[5], hi[6], hi[7]);
            *(float4*)&y[((size_t)b * TT + tb2) * NY + wy * 8]     = o0;
            *(float4*)&y[((size_t)b * TT + tb2) * NY + wy * 8 + 4] = o1;
        }
    }

    // t = 0 output uses z0 directly
    if (bt == 0 && threadIdx.x < NY) {
        int yy = threadIdx.x;
        float s = 0.f;
        #pragma unroll 8
        for (int i = 0; i < NX; i++)
            s = fmaf(g_CzT[i * NY + yy], g_z0[b * NX + i], s);
        #pragma unroll
        for (int k = 0; k < NU; k++)
            s = fmaf(g_DT[k * NY + yy], u[((size_t)b * TT) * NU + k], s);
        y[((size_t)b * TT) * NY + yy] = s;
    }
}

// ---------------- launch -----------------------------------------------------
extern "C" void kernel_launch(void* const* d_in, const int* in_sizes, int n_in,
                              void* d_out, int out_size)
{
    const float* x0   = (const float*)d_in[0];   // (16, 256)
    const float* u    = (const float*)d_in[1];   // (16, 8192, 32)
    const float* Q    = (const float*)d_in[2];   // (256, 256)
    const float* lam  = (const float*)d_in[3];   // (256,)
    const float* Bmat = (const float*)d_in[4];   // (256, 32)
    const float* C    = (const float*)d_in[5];   // (32, 256)
    const float* D    = (const float*)d_in[6];   // (32, 32)
    float* y = (float*)d_out;                    // (16, 8192, 32)

    k0_prep<<<81, 256>>>(x0, Q, lam, Bmat, C, D);
    k1_scan<<<dim3(NC, NB), 64>>>(u, lam);
    k2_boundary<<<NB, 256>>>();
    k3_out<<<dim3(NC / 2, NB), 128>>>(u, y);
}

// round 10
// speedup vs baseline: 1.6295x; 1.0368x over previous
#include <cuda_runtime.h>
#include <cuda_bf16.h>
#include <cstdint>

// Problem constants
#define NB   16      // batch
#define TT   8192    // time steps
#define NX   256     // modal state dim
#define NU   32      // input dim
#define NY   32      // output dim
#define LCH  128     // scan chunk length
#define NC   64      // number of chunks (TT / LCH)

// ---------------- f32x2 packed helpers (sm_103a FFMA2 path) -----------------
__device__ __forceinline__ unsigned long long fma2(unsigned long long a,
                                                   unsigned long long b,
                                                   unsigned long long c) {
    unsigned long long d;
    asm("fma.rn.f32x2 %0, %1, %2, %3;" : "=l"(d) : "l"(a), "l"(b), "l"(c));
    return d;
}
__device__ __forceinline__ unsigned long long pack2(float a, float b) {
    unsigned long long r;
    asm("mov.b64 %0, {%1, %2};" : "=l"(r) : "f"(a), "f"(b));
    return r;
}
__device__ __forceinline__ void unpack2(unsigned long long v, float& a, float& b) {
    asm("mov.b64 {%0, %1}, %2;" : "=f"(a), "=f"(b) : "l"(v));
}

// ---------------- device scratch (no runtime allocation allowed) -----------
__device__ float g_BzT[NU * NX];        // BzT[u][n] = (Q^T Bmat)[n][u]
__device__ float g_CzT[NX * NY];        // CzT[n][y] = (C Q)[y][n]
__device__ float g_z0 [NB * NX];        // modal initial state  x0 @ Q
__device__ float g_DT [NU * NY];        // DT[k][y] = D[y][k]
__device__ float g_lampow[LCH * NX];    // lampow[j][n] = lam[n]^(j+1)
__device__ float g_lamL[NX];            // lam[n]^LCH
__device__ float g_w  [(size_t)NB * TT * NX];   // local chunk scans (134 MB)
__device__ float g_zbprev[NB * NC * NX];        // boundary state feeding chunk c

// ---------------- K0: setup (modal transforms, tables) ----------------------
__global__ void k0_prep(const float* __restrict__ x0,
                        const float* __restrict__ Q,
                        const float* __restrict__ lam,
                        const float* __restrict__ Bmat,
                        const float* __restrict__ C,
                        const float* __restrict__ D)
{
    int n = threadIdx.x;          // 0..255
    int task = blockIdx.x;

    if (task < 32) {
        int u = task;
        float s = 0.f;
        #pragma unroll 8
        for (int i = 0; i < NX; i++)
            s = fmaf(Q[i * NX + n], Bmat[i * NU + u], s);
        g_BzT[u * NX + n] = s;
    } else if (task < 64) {
        int y = task - 32;
        float s = 0.f;
        #pragma unroll 8
        for (int i = 0; i < NX; i++)
            s = fmaf(C[y * NX + i], Q[i * NX + n], s);
        g_CzT[n * NY + y] = s;
    } else if (task < 80) {
        int b = task - 64;
        float s = 0.f;
        #pragma unroll 8
        for (int i = 0; i < NX; i++)
            s = fmaf(x0[b * NX + i], Q[i * NX + n], s);
        g_z0[b * NX + n] = s;
    } else {
        float l = lam[n];
        float p = l;
        for (int j = 0; j < LCH; j++) {
            g_lampow[j * NX + n] = p;       // lam^(j+1)
            if (j == LCH - 1) g_lamL[n] = p;
            p *= l;
        }
        for (int e = threadIdx.x; e < NY * NU; e += blockDim.x) {
            int y = e / NU, k = e % NU;
            g_DT[k * NY + y] = D[y * NU + k];
        }
    }
}

// ---------------- K1: per-chunk local scan, 2 modal lanes per thread --------
__global__ void __launch_bounds__(128) k1_scan(const float* __restrict__ u,
                                               const float* __restrict__ lam)
{
    int c = blockIdx.x;           // chunk
    int b = blockIdx.y;           // batch
    int tid = threadIdx.x;        // 0..127; owns n = tid + 128*m, m=0..1

    __shared__ float4 us4[LCH * (NU / 4)];   // u chunk, 1024 float4 = 16 KB

    const float4* ug = (const float4*)(u + ((size_t)b * TT + (size_t)c * LCH) * NU);
    #pragma unroll
    for (int i = 0; i < 8; i++)                    // FIX: 8*128 = 1024 float4s
        us4[tid + i * 128] = ug[tid + i * 128];

    unsigned long long bz2[2][NU / 2];
    float ln[2], z0c[2], w[2];
    #pragma unroll
    for (int m = 0; m < 2; m++) {
        int n = tid + 128 * m;
        #pragma unroll
        for (int k = 0; k < NU / 2; k++)
            bz2[m][k] = pack2(g_BzT[(2 * k) * NX + n], g_BzT[(2 * k + 1) * NX + n]);
        ln[m]  = lam[n];
        z0c[m] = (c == 0) ? ln[m] * g_z0[b * NX + n] : 0.f;
        w[m]   = 0.f;
    }

    __syncthreads();

    float* wp = g_w + ((size_t)b * TT + (size_t)c * LCH) * NX + tid;
    const ulonglong2* usll = (const ulonglong2*)us4;

    #pragma unroll 4
    for (int j = 0; j < LCH; j++) {
        unsigned long long aA[2] = {0ull, 0ull};
        unsigned long long aB[2] = {0ull, 0ull};
        #pragma unroll
        for (int kk = 0; kk < NU / 4; kk++) {
            ulonglong2 q = usll[j * (NU / 4) + kk];   // broadcast (N=1, cheap)
            #pragma unroll
            for (int m = 0; m < 2; m++) {
                aA[m] = fma2(q.x, bz2[m][2 * kk + 0], aA[m]);
                aB[m] = fma2(q.y, bz2[m][2 * kk + 1], aB[m]);
            }
        }
        #pragma unroll
        for (int m = 0; m < 2; m++) {
            float a0, a1, b0, b1;
            unpack2(aA[m], a0, a1);
            unpack2(aB[m], b0, b1);
            float v = (a0 + a1) + (b0 + b1);
            if (j == 0) v += z0c[m];
            w[m] = fmaf(ln[m], w[m], v);
            wp[(size_t)j * NX + 128 * m] = w[m];      // coalesced over tid
        }
    }
}

// ---------------- K2: chain chunk boundaries (MLP-prefetched) ---------------
__global__ void k2_boundary()
{
    int b = blockIdx.x;
    int n = threadIdx.x;
    float lL = g_lamL[n];
    const float* wp = g_w + ((size_t)b * TT + (LCH - 1)) * NX + n;
    float S[NC];
    #pragma unroll
    for (int c = 0; c < NC; c++)
        S[c] = wp[(size_t)c * LCH * NX];              // 64 independent LDGs
    float* zp = g_zbprev + ((size_t)b * NC) * NX + n;
    float zb = 0.f;
    #pragma unroll
    for (int c = 0; c < NC; c++) {
        zp[(size_t)c * NX] = zb;                      // state entering chunk c
        zb = fmaf(lL, zb, S[c]);
    }
}

// ---------------- K3: correction + fused output GEMM ------------------------
// Block: 128 threads, tile 128t x 32y, K = 256 modal + 32 feedthrough.
// Thread tile 4t x 8y (t-packed FFMA2).  lane = chunk (4 t-rows), warp = y-group.
// z tile XOR-swizzled: word(nn,ch) = nn*128 + (((ch ^ nn) & 31) << 2)
//  -> STS.128 staging and LDS.128 compute both dense + conflict-free.
// __launch_bounds__(128, 6): pin >=6 blocks/SM (reg budget 85/thread).
__global__ void __launch_bounds__(128, 6) k3_out(const float* __restrict__ u,
                                                 float* __restrict__ y)
{
    int c   = blockIdx.x;          // chunk 0..63
    int b   = blockIdx.y;
    int t0  = c * LCH;
    int lane = threadIdx.x & 31;   // chunk index within tile: t = 4*lane+{0..3}
    int wy   = threadIdx.x >> 5;   // y-group: y = 8*wy .. 8*wy+7

    __shared__ float zs [32 * 128];   // swizzled [nn][t] tile (16 KB)
    __shared__ float czs[32 * 32];    // cz tile [nn][y] (4 KB)

    unsigned long long acc[2][8];     // [t-pair][y], packed along t
    #pragma unroll
    for (int p = 0; p < 2; p++)
        #pragma unroll
        for (int q = 0; q < 8; q++) acc[p][q] = 0ull;

    const float* zbp  = g_zbprev + ((size_t)b * NC + c) * NX;
    const size_t wbase = ((size_t)b * TT + t0) * NX;
    const float* ub = u + ((size_t)b * TT + t0 + 1) * NU;
    const int ulim = (c == NC - 1) ? (LCH - 1) * NU : LCH * NU;

    int snn = threadIdx.x & 31;    // staging: row (modal or k index)
    int stg = threadIdx.x >> 5;    // staging: chunk group (8 chunks each)

    for (int nt = 0; nt < 9; nt++) {
        __syncthreads();
        if (nt < 8) {
            int n0 = nt * 32;
            for (int e = threadIdx.x; e < 1024; e += 128)
                czs[e] = g_CzT[n0 * NY + e];
            float zbv = zbp[n0 + snn];
            #pragma unroll
            for (int cc = 0; cc < 8; cc++) {
                int ch = stg * 8 + cc;               // chunk 0..31 (t = 4*ch)
                int tb = ch * 4;
                const float* wrow = &g_w[wbase + (size_t)tb * NX + n0 + snn];
                const float* lrow = &g_lampow[tb * NX + n0 + snn];
                float4 v;
                v.x = fmaf(lrow[0 * NX], zbv, wrow[0 * (size_t)NX]);
                v.y = fmaf(lrow[1 * NX], zbv, wrow[1 * (size_t)NX]);
                v.z = fmaf(lrow[2 * NX], zbv, wrow[2 * (size_t)NX]);
                v.w = fmaf(lrow[3 * NX], zbv, wrow[3 * (size_t)NX]);
                *(float4*)&zs[snn * 128 + (((ch ^ snn) & 31) << 2)] = v;
            }
        } else {
            for (int e = threadIdx.x; e < 1024; e += 128)
                czs[e] = g_DT[e];
            #pragma unroll
            for (int cc = 0; cc < 8; cc++) {
                int ch = stg * 8 + cc;
                int e0 = ch * 4 * NU + snn;          // u element (t*NU + k)
                float4 v;
                v.x = (e0 + 0 * NU < ulim) ? ub[e0 + 0 * NU] : 0.f;
                v.y = (e0 + 1 * NU < ulim) ? ub[e0 + 1 * NU] : 0.f;
                v.z = (e0 + 2 * NU < ulim) ? ub[e0 + 2 * NU] : 0.f;
                v.w = (e0 + 3 * NU < ulim) ? ub[e0 + 3 * NU] : 0.f;
                *(float4*)&zs[snn * 128 + (((ch ^ snn) & 31) << 2)] = v;
            }
        }
        __syncthreads();

        #pragma unroll 4
        for (int nn = 0; nn < 32; nn++) {
            // z: 4 t values, one dense conflict-free LDS.128 per lane
            ulonglong2 za = *(const ulonglong2*)&zs[nn * 128 + (((lane ^ nn) & 31) << 2)];
            // cz: 8 y values, warp-uniform broadcast loads + in-register dup
            float4 c1 = *(const float4*)&czs[nn * 32 + wy * 8];
            float4 c2 = *(const float4*)&czs[nn * 32 + wy * 8 + 4];
            unsigned long long cd[8];
            cd[0] = pack2(c1.x, c1.x); cd[1] = pack2(c1.y, c1.y);
            cd[2] = pack2(c1.z, c1.z); cd[3] = pack2(c1.w, c1.w);
            cd[4] = pack2(c2.x, c2.x); cd[5] = pack2(c2.y, c2.y);
            cd[6] = pack2(c2.z, c2.z); cd[7] = pack2(c2.w, c2.w);
            #pragma unroll
            for (int q = 0; q < 8; q++) {
                acc[0][q] = fma2(za.x, cd[q], acc[0][q]);
                acc[1][q] = fma2(za.y, cd[q], acc[1][q]);
            }
        }
    }

    // store: pair p covers source t = 4*lane + 2p, +1 -> outputs at t0+tsrc+1
    #pragma unroll
    for (int p = 0; p < 2; p++) {
        int tp = 4 * lane + 2 * p;
        float lo[8], hi[8];
        #pragma unroll
        for (int q = 0; q < 8; q++) unpack2(acc[p][q], lo[q], hi[q]);
        int ta = t0 + tp + 1;
        {
            float4 o0 = make_float4(lo[0], lo[1], lo[2], lo[3]);
            float4 o1 = make_float4(lo[4], lo[5], lo[6], lo[7]);
            *(float4*)&y[((size_t)b * TT + ta) * NY + wy * 8]     = o0;
            *(float4*)&y[((size_t)b * TT + ta) * NY + wy * 8 + 4] = o1;
        }
        int tb2 = t0 + tp + 2;
        if (tb2 < TT) {
            float4 o0 = make_float4(hi[0], hi[1], hi[2], hi[3]);
            float4 o1 = make_float4(hi[4], hi[5], hi[6], hi[7]);
            *(float4*)&y[((size_t)b * TT + tb2) * NY + wy * 8]     = o0;
            *(float4*)&y[((size_t)b * TT + tb2) * NY + wy * 8 + 4] = o1;
        }
    }

    // t = 0 output uses z0 directly
    if (c == 0 && threadIdx.x < NY) {
        int yy = threadIdx.x;
        float s = 0.f;
        #pragma unroll 8
        for (int i = 0; i < NX; i++)
            s = fmaf(g_CzT[i * NY + yy], g_z0[b * NX + i], s);
        #pragma unroll
        for (int k = 0; k < NU; k++)
            s = fmaf(g_DT[k * NY + yy], u[((size_t)b * TT) * NU + k], s);
        y[((size_t)b * TT) * NY + yy] = s;
    }
}

// ---------------- launch -----------------------------------------------------
extern "C" void kernel_launch(void* const* d_in, const int* in_sizes, int n_in,
                              void* d_out, int out_size)
{
    const float* x0   = (const float*)d_in[0];   // (16, 256)
    const float* u    = (const float*)d_in[1];   // (16, 8192, 32)
    const float* Q    = (const float*)d_in[2];   // (256, 256)
    const float* lam  = (const float*)d_in[3];   // (256,)
    const float* Bmat = (const float*)d_in[4];   // (256, 32)
    const float* C    = (const float*)d_in[5];   // (32, 256)
    const float* D    = (const float*)d_in[6];   // (32, 32)
    float* y = (float*)d_out;                    // (16, 8192, 32)

    k0_prep<<<81, 256>>>(x0, Q, lam, Bmat, C, D);
    k1_scan<<<dim3(NC, NB), 128>>>(u, lam);
    k2_boundary<<<NB, 256>>>();
    k3_out<<<dim3(NC, NB), 128>>>(u, y);
}

// round 16
// speedup vs baseline: 1.9448x; 1.1935x over previous
#include <cuda_runtime.h>
#include <cuda_bf16.h>
#include <cstdint>

// Problem constants
#define NB   16      // batch
#define TT   8192    // time steps
#define NX   256     // modal state dim
#define NU   32      // input dim
#define NY   32      // output dim
#define LCH  128     // scan chunk length
#define NC   64      // number of chunks (TT / LCH)

// ---------------- f32x2 packed helpers (sm_103a FFMA2 path) -----------------
__device__ __forceinline__ unsigned long long fma2(unsigned long long a,
                                                   unsigned long long b,
                                                   unsigned long long c) {
    unsigned long long d;
    asm("fma.rn.f32x2 %0, %1, %2, %3;" : "=l"(d) : "l"(a), "l"(b), "l"(c));
    return d;
}
__device__ __forceinline__ unsigned long long pack2(float a, float b) {
    unsigned long long r;
    asm("mov.b64 %0, {%1, %2};" : "=l"(r) : "f"(a), "f"(b));
    return r;
}
__device__ __forceinline__ void unpack2(unsigned long long v, float& a, float& b) {
    asm("mov.b64 {%0, %1}, %2;" : "=f"(a), "=f"(b) : "l"(v));
}

// ---------------- device scratch (no runtime allocation allowed) -----------
__device__ float g_BzT[NU * NX];        // BzT[u][n] = (Q^T Bmat)[n][u]
__device__ float g_CzT[NX * NY];        // CzT[n][y] = (C Q)[y][n]
__device__ float g_CzD[NX * 2 * NY];    // dup pairs: CzD[n][2y]=CzD[n][2y+1]=Cz[y][n]
__device__ float g_DTD[NU * 2 * NY];    // dup pairs: DTD[k][2y]=DTD[k][2y+1]=D[y][k]
__device__ float g_z0 [NB * NX];        // modal initial state  x0 @ Q
__device__ float g_DT [NU * NY];        // DT[k][y] = D[y][k]
__device__ float g_lampow[LCH * NX];    // lampow[j][n] = lam[n]^(j+1)
__device__ float g_lamL[NX];            // lam[n]^LCH
__device__ float g_w  [(size_t)NB * TT * NX];   // local chunk scans (134 MB)
__device__ float g_zbprev[NB * NC * NX];        // boundary state feeding chunk c

// ---------------- K0: setup (modal transforms, tables) ----------------------
__global__ void k0_prep(const float* __restrict__ x0,
                        const float* __restrict__ Q,
                        const float* __restrict__ lam,
                        const float* __restrict__ Bmat,
                        const float* __restrict__ C,
                        const float* __restrict__ D)
{
    int n = threadIdx.x;          // 0..255
    int task = blockIdx.x;

    if (task < 32) {
        int u = task;
        float s = 0.f;
        #pragma unroll 8
        for (int i = 0; i < NX; i++)
            s = fmaf(Q[i * NX + n], Bmat[i * NU + u], s);
        g_BzT[u * NX + n] = s;
    } else if (task < 64) {
        int y = task - 32;
        float s = 0.f;
        #pragma unroll 8
        for (int i = 0; i < NX; i++)
            s = fmaf(C[y * NX + i], Q[i * NX + n], s);
        g_CzT[n * NY + y] = s;
    } else if (task < 80) {
        int b = task - 64;
        float s = 0.f;
        #pragma unroll 8
        for (int i = 0; i < NX; i++)
            s = fmaf(x0[b * NX + i], Q[i * NX + n], s);
        g_z0[b * NX + n] = s;
    } else if (task < 112) {
        // duplicated-pair Cz table (independent recompute; no ordering hazard)
        int y = task - 80;
        float s = 0.f;
        #pragma unroll 8
        for (int i = 0; i < NX; i++)
            s = fmaf(C[y * NX + i], Q[i * NX + n], s);
        g_CzD[n * 64 + 2 * y]     = s;
        g_CzD[n * 64 + 2 * y + 1] = s;
    } else if (task < 113) {
        // duplicated-pair D^T table
        for (int e = threadIdx.x; e < NY * NU; e += blockDim.x) {
            int y = e / NU, k = e % NU;
            g_DTD[k * 64 + 2 * y]     = D[y * NU + k];
            g_DTD[k * 64 + 2 * y + 1] = D[y * NU + k];
        }
    } else {
        float l = lam[n];
        float p = l;
        for (int j = 0; j < LCH; j++) {
            g_lampow[j * NX + n] = p;       // lam^(j+1)
            if (j == LCH - 1) g_lamL[n] = p;
            p *= l;
        }
        for (int e = threadIdx.x; e < NY * NU; e += blockDim.x) {
            int y = e / NU, k = e % NU;
            g_DT[k * NY + y] = D[y * NU + k];
        }
    }
}

// ---------------- K1: per-chunk local scan, 2 modal lanes per thread --------
__global__ void __launch_bounds__(128) k1_scan(const float* __restrict__ u,
                                               const float* __restrict__ lam)
{
    int c = blockIdx.x;           // chunk
    int b = blockIdx.y;           // batch
    int tid = threadIdx.x;        // 0..127; owns n = tid + 128*m, m=0..1

    __shared__ float4 us4[LCH * (NU / 4)];   // u chunk, 1024 float4 = 16 KB

    const float4* ug = (const float4*)(u + ((size_t)b * TT + (size_t)c * LCH) * NU);
    #pragma unroll
    for (int i = 0; i < 8; i++)                    // 8*128 = 1024 float4s
        us4[tid + i * 128] = ug[tid + i * 128];

    unsigned long long bz2[2][NU / 2];
    float ln[2], z0c[2], w[2];
    #pragma unroll
    for (int m = 0; m < 2; m++) {
        int n = tid + 128 * m;
        #pragma unroll
        for (int k = 0; k < NU / 2; k++)
            bz2[m][k] = pack2(g_BzT[(2 * k) * NX + n], g_BzT[(2 * k + 1) * NX + n]);
        ln[m]  = lam[n];
        z0c[m] = (c == 0) ? ln[m] * g_z0[b * NX + n] : 0.f;
        w[m]   = 0.f;
    }

    __syncthreads();

    float* wp = g_w + ((size_t)b * TT + (size_t)c * LCH) * NX + tid;
    const ulonglong2* usll = (const ulonglong2*)us4;

    #pragma unroll 4
    for (int j = 0; j < LCH; j++) {
        unsigned long long aA[2] = {0ull, 0ull};
        unsigned long long aB[2] = {0ull, 0ull};
        #pragma unroll
        for (int kk = 0; kk < NU / 4; kk++) {
            ulonglong2 q = usll[j * (NU / 4) + kk];   // broadcast (N=1, cheap)
            #pragma unroll
            for (int m = 0; m < 2; m++) {
                aA[m] = fma2(q.x, bz2[m][2 * kk + 0], aA[m]);
                aB[m] = fma2(q.y, bz2[m][2 * kk + 1], aB[m]);
            }
        }
        #pragma unroll
        for (int m = 0; m < 2; m++) {
            float a0, a1, b0, b1;
            unpack2(aA[m], a0, a1);
            unpack2(aB[m], b0, b1);
            float v = (a0 + a1) + (b0 + b1);
            if (j == 0) v += z0c[m];
            w[m] = fmaf(ln[m], w[m], v);
            wp[(size_t)j * NX + 128 * m] = w[m];      // coalesced over tid
        }
    }
}

// ---------------- K2: chain chunk boundaries (MLP-prefetched) ---------------
__global__ void k2_boundary()
{
    int b = blockIdx.x;
    int n = threadIdx.x;
    float lL = g_lamL[n];
    const float* wp = g_w + ((size_t)b * TT + (LCH - 1)) * NX + n;
    float S[NC];
    #pragma unroll
    for (int c = 0; c < NC; c++)
        S[c] = wp[(size_t)c * LCH * NX];              // 64 independent LDGs
    float* zp = g_zbprev + ((size_t)b * NC) * NX + n;
    float zb = 0.f;
    #pragma unroll
    for (int c = 0; c < NC; c++) {
        zp[(size_t)c * NX] = zb;                      // state entering chunk c
        zb = fmaf(lL, zb, S[c]);
    }
}

// ---------------- K3: correction + fused output GEMM (pipelined) ------------
// Block: 128 threads, tile 128t x 32y, K = 256 modal + 32 feedthrough tiles.
// Thread tile 4t x 8y, t-packed FFMA2; cz comes pre-duplicated from smem czd
// (no pack2 MOVs in inner loop). Staging double-buffered: next tile's g_w is
// prefetched into registers during compute; ONE __syncthreads per tile.
__global__ void __launch_bounds__(128, 4) k3_out(const float* __restrict__ u,
                                                 float* __restrict__ y)
{
    int c   = blockIdx.x;          // chunk 0..63
    int b   = blockIdx.y;
    int t0  = c * LCH;
    int lane = threadIdx.x & 31;   // chunk index within tile: t = 4*lane+{0..3}
    int wy   = threadIdx.x >> 5;   // y-group: y = 8*wy .. 8*wy+7

    __shared__ float zs [2][32 * 128];   // swizzled [nn][t] tiles (2x16 KB)
    __shared__ float czd[2][32 * 64];    // dup-pair cz tiles [nn][2y] (2x8 KB)

    unsigned long long acc[2][8];        // [t-pair][y], packed along t
    #pragma unroll
    for (int p = 0; p < 2; p++)
        #pragma unroll
        for (int q = 0; q < 8; q++) acc[p][q] = 0ull;

    const float* zbp  = g_zbprev + ((size_t)b * NC + c) * NX;
    const size_t wbase = ((size_t)b * TT + t0) * NX;
    const float* ub = u + ((size_t)b * TT + t0 + 1) * NU;
    const int ulim = (c == NC - 1) ? (LCH - 1) * NU : LCH * NU;

    int snn = threadIdx.x & 31;    // staging: row (modal or k index)
    int stg = threadIdx.x >> 5;    // staging: chunk group (8 chunks each)

    float pw[32];                  // prefetch registers for next tile

    // ---- prefetch + stage tile 0 ----
    #pragma unroll
    for (int cc = 0; cc < 8; cc++) {
        int tb = (stg * 8 + cc) * 4;
        const float* wrow = &g_w[wbase + (size_t)tb * NX + snn];
        #pragma unroll
        for (int r = 0; r < 4; r++) pw[cc * 4 + r] = wrow[(size_t)r * NX];
    }
    {
        float zbv = zbp[snn];
        #pragma unroll
        for (int cc = 0; cc < 8; cc++) {
            int ch = stg * 8 + cc;
            int tb = ch * 4;
            const float* lrow = &g_lampow[tb * NX + snn];
            float4 v;
            v.x = fmaf(lrow[0 * NX], zbv, pw[cc * 4 + 0]);
            v.y = fmaf(lrow[1 * NX], zbv, pw[cc * 4 + 1]);
            v.z = fmaf(lrow[2 * NX], zbv, pw[cc * 4 + 2]);
            v.w = fmaf(lrow[3 * NX], zbv, pw[cc * 4 + 3]);
            *(float4*)&zs[0][snn * 128 + (((ch ^ snn) & 31) << 2)] = v;
        }
        const float4* src = (const float4*)&g_CzD[0];
        #pragma unroll
        for (int e = 0; e < 4; e++)
            ((float4*)czd[0])[threadIdx.x + e * 128] = src[threadIdx.x + e * 128];
    }
    __syncthreads();

    for (int nt = 0; nt < 9; nt++) {
        int buf = nt & 1;

        // ---- issue prefetch LDGs for tile nt+1 (latency hidden by compute) ----
        if (nt < 7) {
            int n0 = (nt + 1) * 32;
            #pragma unroll
            for (int cc = 0; cc < 8; cc++) {
                int tb = (stg * 8 + cc) * 4;
                const float* wrow = &g_w[wbase + (size_t)tb * NX + n0 + snn];
                #pragma unroll
                for (int r = 0; r < 4; r++) pw[cc * 4 + r] = wrow[(size_t)r * NX];
            }
        } else if (nt == 7) {
            #pragma unroll
            for (int cc = 0; cc < 8; cc++) {
                int e0 = (stg * 8 + cc) * 4 * NU + snn;
                #pragma unroll
                for (int r = 0; r < 4; r++)
                    pw[cc * 4 + r] = (e0 + r * NU < ulim) ? ub[e0 + r * NU] : 0.f;
            }
        }

        // ---- compute over tile nt ----
        #pragma unroll 4
        for (int nn = 0; nn < 32; nn++) {
            ulonglong2 za = *(const ulonglong2*)&zs[buf][nn * 128 + (((lane ^ nn) & 31) << 2)];
            const float* crow = &czd[buf][nn * 64 + wy * 16];
            ulonglong2 cA = *(const ulonglong2*)(crow);       // y dups 0,1
            ulonglong2 cB = *(const ulonglong2*)(crow + 4);   // y dups 2,3
            ulonglong2 cC = *(const ulonglong2*)(crow + 8);   // y dups 4,5
            ulonglong2 cD = *(const ulonglong2*)(crow + 12);  // y dups 6,7
            acc[0][0] = fma2(za.x, cA.x, acc[0][0]);
            acc[1][0] = fma2(za.y, cA.x, acc[1][0]);
            acc[0][1] = fma2(za.x, cA.y, acc[0][1]);
            acc[1][1] = fma2(za.y, cA.y, acc[1][1]);
            acc[0][2] = fma2(za.x, cB.x, acc[0][2]);
            acc[1][2] = fma2(za.y, cB.x, acc[1][2]);
            acc[0][3] = fma2(za.x, cB.y, acc[0][3]);
            acc[1][3] = fma2(za.y, cB.y, acc[1][3]);
            acc[0][4] = fma2(za.x, cC.x, acc[0][4]);
            acc[1][4] = fma2(za.y, cC.x, acc[1][4]);
            acc[0][5] = fma2(za.x, cC.y, acc[0][5]);
            acc[1][5] = fma2(za.y, cC.y, acc[1][5]);
            acc[0][6] = fma2(za.x, cD.x, acc[0][6]);
            acc[1][6] = fma2(za.y, cD.x, acc[1][6]);
            acc[0][7] = fma2(za.x, cD.y, acc[0][7]);
            acc[1][7] = fma2(za.y, cD.y, acc[1][7]);
        }

        // ---- stage tile nt+1 into the other buffer ----
        if (nt < 8) {
            int bf = buf ^ 1;
            if (nt < 7) {
                int n0 = (nt + 1) * 32;
                float zbv = zbp[n0 + snn];
                #pragma unroll
                for (int cc = 0; cc < 8; cc++) {
                    int ch = stg * 8 + cc;
                    int tb = ch * 4;
                    const float* lrow = &g_lampow[tb * NX + n0 + snn];
                    float4 v;
                    v.x = fmaf(lrow[0 * NX], zbv, pw[cc * 4 + 0]);
                    v.y = fmaf(lrow[1 * NX], zbv, pw[cc * 4 + 1]);
                    v.z = fmaf(lrow[2 * NX], zbv, pw[cc * 4 + 2]);
                    v.w = fmaf(lrow[3 * NX], zbv, pw[cc * 4 + 3]);
                    *(float4*)&zs[bf][snn * 128 + (((ch ^ snn) & 31) << 2)] = v;
                }
                const float4* src = (const float4*)&g_CzD[n0 * 64];
                #pragma unroll
                for (int e = 0; e < 4; e++)
                    ((float4*)czd[bf])[threadIdx.x + e * 128] = src[threadIdx.x + e * 128];
            } else {
                // feedthrough tile: raw u rows + dup D^T
                #pragma unroll
                for (int cc = 0; cc < 8; cc++) {
                    int ch = stg * 8 + cc;
                    float4 v = make_float4(pw[cc * 4 + 0], pw[cc * 4 + 1],
                                           pw[cc * 4 + 2], pw[cc * 4 + 3]);
                    *(float4*)&zs[bf][snn * 128 + (((ch ^ snn) & 31) << 2)] = v;
                }
                const float4* src = (const float4*)&g_DTD[0];
                #pragma unroll
                for (int e = 0; e < 4; e++)
                    ((float4*)czd[bf])[threadIdx.x + e * 128] = src[threadIdx.x + e * 128];
            }
            __syncthreads();
        }
    }

    // store: pair p covers source t = 4*lane + 2p, +1 -> outputs at t0+tsrc+1
    #pragma unroll
    for (int p = 0; p < 2; p++) {
        int tp = 4 * lane + 2 * p;
        float lo[8], hi[8];
        #pragma unroll
        for (int q = 0; q < 8; q++) unpack2(acc[p][q], lo[q], hi[q]);
        int ta = t0 + tp + 1;
        {
            float4 o0 = make_float4(lo[0], lo[1], lo[2], lo[3]);
            float4 o1 = make_float4(lo[4], lo[5], lo[6], lo[7]);
            *(float4*)&y[((size_t)b * TT + ta) * NY + wy * 8]     = o0;
            *(float4*)&y[((size_t)b * TT + ta) * NY + wy * 8 + 4] = o1;
        }
        int tb2 = t0 + tp + 2;
        if (tb2 < TT) {
            float4 o0 = make_float4(hi[0], hi[1], hi[2], hi[3]);
            float4 o1 = make_float4(hi[4], hi[5], hi[6], hi[7]);
            *(float4*)&y[((size_t)b * TT + tb2) * NY + wy * 8]     = o0;
            *(float4*)&y[((size_t)b * TT + tb2) * NY + wy * 8 + 4] = o1;
        }
    }

    // t = 0 output uses z0 directly
    if (c == 0 && threadIdx.x < NY) {
        int yy = threadIdx.x;
        float s = 0.f;
        #pragma unroll 8
        for (int i = 0; i < NX; i++)
            s = fmaf(g_CzT[i * NY + yy], g_z0[b * NX + i], s);
        #pragma unroll
        for (int k = 0; k < NU; k++)
            s = fmaf(g_DT[k * NY + yy], u[((size_t)b * TT) * NU + k], s);
        y[((size_t)b * TT) * NY + yy] = s;
    }
}

// ---------------- launch -----------------------------------------------------
extern "C" void kernel_launch(void* const* d_in, const int* in_sizes, int n_in,
                              void* d_out, int out_size)
{
    const float* x0   = (const float*)d_in[0];   // (16, 256)
    const float* u    = (const float*)d_in[1];   // (16, 8192, 32)
    const float* Q    = (const float*)d_in[2];   // (256, 256)
    const float* lam  = (const float*)d_in[3];   // (256,)
    const float* Bmat = (const float*)d_in[4];   // (256, 32)
    const float* C    = (const float*)d_in[5];   // (32, 256)
    const float* D    = (const float*)d_in[6];   // (32, 32)
    float* y = (float*)d_out;                    // (16, 8192, 32)

    k0_prep<<<114, 256>>>(x0, Q, lam, Bmat, C, D);
    k1_scan<<<dim3(NC, NB), 128>>>(u, lam);
    k2_boundary<<<NB, 256>>>();
    k3_out<<<dim3(NC, NB), 128>>>(u, y);
}